// round 3
// baseline (speedup 1.0000x reference)
#include <cuda_runtime.h>
#include <mma.h>

using namespace nvcuda;

#define T_LEN 1024
#define BATCH 32
#define HID   512
#define G3    1536
#define TBm   (T_LEN*BATCH)

// Scratch (allocation-free rule: static __device__ arrays)
__device__ float g_gi[2][(size_t)TBm * G3];     // per-layer gi, fwd/bwd
__device__ float g_buf[2][(size_t)TBm * 1024];  // layer output ping-pong
__device__ float g_hbuf[2][2][BATCH * HID];     // [dir][pingpong]
__device__ int   g_bar;

// ---------------------------------------------------------------------------
// Input GEMM: Gi[M, 1536] = A[M, K] * W[1536, K]^T   (tf32 wmma, no bias —
// biases are folded into the recurrent kernel's gate math)
// ---------------------------------------------------------------------------
__global__ __launch_bounds__(128) void gi_gemm(const float* __restrict__ A,
                                               const float* __restrict__ W,
                                               float* __restrict__ Gi, int K)
{
    const int warpId = threadIdx.x >> 5;
    const int warpM  = warpId & 1;
    const int warpN  = warpId >> 1;
    const int m0 = blockIdx.y * 64 + warpM * 32;
    const int n0 = blockIdx.x * 64 + warpN * 32;

    wmma::fragment<wmma::accumulator, 16, 16, 8, float> acc[2][2];
#pragma unroll
    for (int i = 0; i < 2; i++)
#pragma unroll
        for (int j = 0; j < 2; j++) wmma::fill_fragment(acc[i][j], 0.f);

    for (int k = 0; k < K; k += 8) {
        wmma::fragment<wmma::matrix_a, 16, 16, 8, wmma::precision::tf32, wmma::row_major> af[2];
        wmma::fragment<wmma::matrix_b, 16, 16, 8, wmma::precision::tf32, wmma::col_major> bf[2];
#pragma unroll
        for (int i = 0; i < 2; i++) {
            wmma::load_matrix_sync(af[i], A + (size_t)(m0 + 16 * i) * K + k, K);
#pragma unroll
            for (int e = 0; e < af[i].num_elements; e++)
                af[i].x[e] = wmma::__float_to_tf32(af[i].x[e]);
        }
#pragma unroll
        for (int j = 0; j < 2; j++) {
            // W is (1536 x K) row-major; interpreted as (K x 1536) col-major, ld = K
            wmma::load_matrix_sync(bf[j], W + (size_t)(n0 + 16 * j) * K + k, K);
#pragma unroll
            for (int e = 0; e < bf[j].num_elements; e++)
                bf[j].x[e] = wmma::__float_to_tf32(bf[j].x[e]);
        }
#pragma unroll
        for (int i = 0; i < 2; i++)
#pragma unroll
            for (int j = 0; j < 2; j++)
                wmma::mma_sync(acc[i][j], af[i], bf[j], acc[i][j]);
    }
#pragma unroll
    for (int i = 0; i < 2; i++)
#pragma unroll
        for (int j = 0; j < 2; j++)
            wmma::store_matrix_sync(Gi + (size_t)(m0 + 16 * i) * G3 + n0 + 16 * j,
                                    acc[i][j], G3, wmma::mem_row_major);
}

// ---------------------------------------------------------------------------
// Persistent recurrent scan for one layer (both directions).
// Grid = 128 CTAs: blockIdx>>6 = direction, (blockIdx&63)*8 = h-column slice.
// Whh slice (24 rows x 512) lives in SMEM for all 1024 steps.
// One grid-wide spin barrier per step; h ping-pongs in global, read via ldcg.
// ---------------------------------------------------------------------------
#define SH_H 520                    // h row stride (floats): conflict-free
#define SH_W 524                    // w row stride (floats): conflict-free
#define SMEM_BYTES ((32 * SH_H + 24 * SH_W) * 4)

__global__ __launch_bounds__(256, 1) void gru_scan(
    const float* __restrict__ gi_f, const float* __restrict__ gi_b,
    const float* __restrict__ whh_f, const float* __restrict__ whh_b,
    const float* __restrict__ bih_f, const float* __restrict__ bhh_f,
    const float* __restrict__ bih_b, const float* __restrict__ bhh_b,
    const float* __restrict__ h0_f, const float* __restrict__ h0_b,
    float* __restrict__ out,
    float* __restrict__ fin_f, float* __restrict__ fin_b)
{
    extern __shared__ float smem[];
    float* sh_h = smem;                 // 32 x SH_H
    float* sh_w = smem + 32 * SH_H;     // 24 x SH_W

    const int tid = threadIdx.x;
    const int dir = blockIdx.x >> 6;
    const int c0  = (blockIdx.x & 63) * 8;

    const float* gi  = dir ? gi_b  : gi_f;
    const float* whh = dir ? whh_b : whh_f;
    const float* bih = dir ? bih_b : bih_f;
    const float* bhh = dir ? bhh_b : bhh_f;
    const float* h0  = dir ? h0_b  : h0_f;
    float* fin = dir ? fin_b : fin_f;

    // Cache weight slice: rows {j, 512+j, 1024+j} for j in [c0, c0+8)
    for (int idx = tid; idx < 24 * 512; idx += 256) {
        int row = idx >> 9, col = idx & 511;
        int gate = row >> 3, jr = row & 7;
        sh_w[row * SH_W + col] = whh[(size_t)(gate * 512 + c0 + jr) * 512 + col];
    }

    const int lane = tid & 31;
    const int b  = (tid >> 5) * 4 + (lane >> 3);  // 0..31
    const int jj = lane & 7;
    const int j  = c0 + jj;

    const float bhr = bhh[j], bhz = bhh[512 + j], bhn = bhh[1024 + j];
    const float bir = bih[j], biz = bih[512 + j], bin_ = bih[1024 + j];

    const float4* w4 = reinterpret_cast<const float4*>(sh_w) + jj * (SH_W / 4);
    const float4* h4 = reinterpret_cast<const float4*>(sh_h) + b * (SH_H / 4);

    for (int s = 0; s < 1024; ++s) {
        const int t = dir ? (1023 - s) : s;
        const float* hsrc = (s == 0) ? h0 : &g_hbuf[dir][s & 1][0];

        // Cooperative load of full h (32x512) into SMEM (L2-fresh via ldcg)
        const float4* src4 = reinterpret_cast<const float4*>(hsrc);
#pragma unroll
        for (int i = 0; i < 16; ++i) {
            int flat = tid + i * 256;            // 0..4095 float4s
            int row = flat >> 7, c4 = flat & 127;
            reinterpret_cast<float4*>(sh_h)[row * (SH_H / 4) + c4] =
                __ldcg(src4 + row * 128 + c4);
        }
        __syncthreads();

        float ar = 0.f, az = 0.f, an = 0.f;
#pragma unroll 4
        for (int kq = 0; kq < 128; ++kq) {
            float4 hv = h4[kq];
            float4 w0 = w4[kq];
            float4 w1 = w4[kq + 8 * (SH_W / 4)];
            float4 w2 = w4[kq + 16 * (SH_W / 4)];
            ar += hv.x * w0.x + hv.y * w0.y + hv.z * w0.z + hv.w * w0.w;
            az += hv.x * w1.x + hv.y * w1.y + hv.z * w1.z + hv.w * w1.w;
            an += hv.x * w2.x + hv.y * w2.y + hv.z * w2.z + hv.w * w2.w;
        }

        const float ghr = ar + bhr, ghz = az + bhz, ghn = an + bhn;
        const float* gip = gi + ((size_t)t * BATCH + b) * G3;
        const float xr = gip[j] + bir;
        const float xz = gip[512 + j] + biz;
        const float xn = gip[1024 + j] + bin_;

        const float r = 1.f / (1.f + __expf(-(xr + ghr)));
        const float z = 1.f / (1.f + __expf(-(xz + ghz)));
        const float n = tanhf(xn + r * ghn);
        const float hold = sh_h[b * SH_H + j];
        const float hn = (1.f - z) * n + z * hold;

        g_hbuf[dir][(s + 1) & 1][b * HID + j] = hn;
        out[((size_t)t * BATCH + b) * 1024 + dir * 512 + j] = hn;
        if (s == 1023) fin[b * HID + j] = hn;

        // grid barrier: all CTAs (both directions) step in lockstep
        __threadfence();
        __syncthreads();
        if (tid == 0) {
            atomicAdd(&g_bar, 1);
            const int target = (s + 1) * (int)gridDim.x;
            while (*((volatile int*)&g_bar) < target) __nanosleep(64);
        }
        __syncthreads();
    }
}

// ---------------------------------------------------------------------------
extern "C" void kernel_launch(void* const* d_in, const int* in_sizes, int n_in,
                              void* d_out, int out_size)
{
    const float* x  = (const float*)d_in[0];
    const float* h0 = (const float*)d_in[1];
    float* out    = (float*)d_out;
    float* finals = out + (size_t)TBm * 1024;

    float* gi_base; float* buf_base; void* barp;
    cudaGetSymbolAddress((void**)&gi_base, g_gi);
    cudaGetSymbolAddress((void**)&buf_base, g_buf);
    cudaGetSymbolAddress(&barp, g_bar);
    float* gi_f = gi_base;
    float* gi_b = gi_base + (size_t)TBm * G3;
    float* bufA = buf_base;
    float* bufB = buf_base + (size_t)TBm * 1024;

    cudaFuncSetAttribute(gru_scan, cudaFuncAttributeMaxDynamicSharedMemorySize,
                         SMEM_BYTES);

    const float* lin = x;
    int K = 256;
    for (int layer = 0; layer < 3; ++layer) {
        const float* wih_f = (const float*)d_in[2 + 8 * layer + 0];
        const float* whh_f = (const float*)d_in[2 + 8 * layer + 1];
        const float* bih_f = (const float*)d_in[2 + 8 * layer + 2];
        const float* bhh_f = (const float*)d_in[2 + 8 * layer + 3];
        const float* wih_b = (const float*)d_in[2 + 8 * layer + 4];
        const float* whh_b = (const float*)d_in[2 + 8 * layer + 5];
        const float* bih_b = (const float*)d_in[2 + 8 * layer + 6];
        const float* bhh_b = (const float*)d_in[2 + 8 * layer + 7];

        dim3 grid(G3 / 64, TBm / 64);
        gi_gemm<<<grid, 128>>>(lin, wih_f, gi_f, K);
        gi_gemm<<<grid, 128>>>(lin, wih_b, gi_b, K);

        cudaMemsetAsync(barp, 0, sizeof(int));

        float* lout = (layer == 0) ? bufA : (layer == 1) ? bufB : out;
        gru_scan<<<128, 256, SMEM_BYTES>>>(
            gi_f, gi_b, whh_f, whh_b,
            bih_f, bhh_f, bih_b, bhh_b,
            h0 + (size_t)(2 * layer) * BATCH * HID,
            h0 + (size_t)(2 * layer + 1) * BATCH * HID,
            lout,
            finals + (size_t)(2 * layer) * BATCH * HID,
            finals + (size_t)(2 * layer + 1) * BATCH * HID);

        lin = lout;
        K = 1024;
    }
}

// round 4
// speedup vs baseline: 1.2561x; 1.2561x over previous
#include <cuda_runtime.h>
#include <mma.h>

using namespace nvcuda;

#define T_LEN 1024
#define BATCH 32
#define HID   512
#define G3    1536
#define TBm   (T_LEN*BATCH)

// Scratch (allocation-free rule: static __device__ arrays)
__device__ float g_gi[2][(size_t)TBm * G3];     // per-layer gi, fwd/bwd
__device__ float g_buf[2][(size_t)TBm * 1024];  // layer output ping-pong
__device__ float g_hbuf[2][2][BATCH * HID];     // [dir][pingpong]
__device__ int   g_flags[2][64 * 32];           // per-CTA step flags, 128B-padded

// ---------------------------------------------------------------------------
// Input GEMM: Gi[M, 1536] = A[M, K] * W[1536, K]^T   (tf32 wmma, no bias —
// biases are folded into the recurrent kernel's gate math). Unchanged from R3.
// ---------------------------------------------------------------------------
__global__ __launch_bounds__(128) void gi_gemm(const float* __restrict__ A,
                                               const float* __restrict__ W,
                                               float* __restrict__ Gi, int K)
{
    const int warpId = threadIdx.x >> 5;
    const int warpM  = warpId & 1;
    const int warpN  = warpId >> 1;
    const int m0 = blockIdx.y * 64 + warpM * 32;
    const int n0 = blockIdx.x * 64 + warpN * 32;

    wmma::fragment<wmma::accumulator, 16, 16, 8, float> acc[2][2];
#pragma unroll
    for (int i = 0; i < 2; i++)
#pragma unroll
        for (int j = 0; j < 2; j++) wmma::fill_fragment(acc[i][j], 0.f);

    for (int k = 0; k < K; k += 8) {
        wmma::fragment<wmma::matrix_a, 16, 16, 8, wmma::precision::tf32, wmma::row_major> af[2];
        wmma::fragment<wmma::matrix_b, 16, 16, 8, wmma::precision::tf32, wmma::col_major> bf[2];
#pragma unroll
        for (int i = 0; i < 2; i++) {
            wmma::load_matrix_sync(af[i], A + (size_t)(m0 + 16 * i) * K + k, K);
#pragma unroll
            for (int e = 0; e < af[i].num_elements; e++)
                af[i].x[e] = wmma::__float_to_tf32(af[i].x[e]);
        }
#pragma unroll
        for (int j = 0; j < 2; j++) {
            wmma::load_matrix_sync(bf[j], W + (size_t)(n0 + 16 * j) * K + k, K);
#pragma unroll
            for (int e = 0; e < bf[j].num_elements; e++)
                bf[j].x[e] = wmma::__float_to_tf32(bf[j].x[e]);
        }
#pragma unroll
        for (int i = 0; i < 2; i++)
#pragma unroll
            for (int j = 0; j < 2; j++)
                wmma::mma_sync(acc[i][j], af[i], bf[j], acc[i][j]);
    }
#pragma unroll
    for (int i = 0; i < 2; i++)
#pragma unroll
        for (int j = 0; j < 2; j++)
            wmma::store_matrix_sync(Gi + (size_t)(m0 + 16 * i) * G3 + n0 + 16 * j,
                                    acc[i][j], G3, wmma::mem_row_major);
}

// ---------------------------------------------------------------------------
// Persistent recurrent scan for one layer (both directions).
// Grid = 128 CTAs x 128 threads: blockIdx>>6 = direction, (blockIdx&63)*8 = j-slice.
// Each thread handles 2 batch rows (b, b+16) for one j -> FFMA2 packed math.
// Whh slice (24 rows x 512) lives in SMEM for all 1024 steps.
// Flag-array barrier per direction; gi prefetched before the spin.
// ---------------------------------------------------------------------------
#define SH_H 520                    // h row stride (floats): conflict-free
#define SH_W 524                    // w row stride (floats): conflict-free
#define SMEM_BYTES ((32 * SH_H + 24 * SH_W) * 4)

#define FMA2(acc, a, b) \
    asm("fma.rn.f32x2 %0, %1, %2, %0;" : "+l"(acc) : "l"(a), "l"(b))

__device__ __forceinline__ float rsum2(unsigned long long a, unsigned long long b)
{
    float2 fa = *reinterpret_cast<float2*>(&a);
    float2 fb = *reinterpret_cast<float2*>(&b);
    return (fa.x + fa.y) + (fb.x + fb.y);
}

__global__ __launch_bounds__(128, 1) void gru_scan(
    const float* __restrict__ gi_f, const float* __restrict__ gi_b,
    const float* __restrict__ whh_f, const float* __restrict__ whh_b,
    const float* __restrict__ bih_f, const float* __restrict__ bhh_f,
    const float* __restrict__ bih_b, const float* __restrict__ bhh_b,
    const float* __restrict__ h0_f, const float* __restrict__ h0_b,
    float* __restrict__ out,
    float* __restrict__ fin_f, float* __restrict__ fin_b)
{
    extern __shared__ float smem[];
    float* sh_h = smem;                 // 32 x SH_H
    float* sh_w = smem + 32 * SH_H;     // 24 x SH_W

    const int tid = threadIdx.x;
    const int dir = blockIdx.x >> 6;
    const int cta = blockIdx.x & 63;
    const int c0  = cta * 8;

    const float* gi  = dir ? gi_b  : gi_f;
    const float* whh = dir ? whh_b : whh_f;
    const float* bih = dir ? bih_b : bih_f;
    const float* bhh = dir ? bhh_b : bhh_f;
    const float* h0  = dir ? h0_b  : h0_f;
    float* fin = dir ? fin_b : fin_f;
    volatile int* flags = (volatile int*)g_flags[dir];

    // Cache weight slice (gate-major rows {g*512 + c0 + jr}), vectorized.
    {
        const float4* wsrc = reinterpret_cast<const float4*>(whh);
#pragma unroll
        for (int it = 0; it < 24; ++it) {
            int idx = tid + it * 128;            // 0..3071 float4s
            int row = idx >> 7, c4 = idx & 127;
            int gate = row >> 3, jr = row & 7;
            reinterpret_cast<float4*>(sh_w)[row * (SH_W / 4) + c4] =
                __ldg(wsrc + (size_t)(gate * 512 + c0 + jr) * 128 + c4);
        }
    }

    const int jj = tid & 7;
    const int bp = tid >> 3;            // 0..15
    const int b0 = bp, b1 = bp + 16;
    const int j  = c0 + jj;

    const float bhr = bhh[j], bhz = bhh[512 + j], bhn = bhh[1024 + j];
    const float bir = bih[j], biz = bih[512 + j], bin_ = bih[1024 + j];

    const ulonglong2* wr4 = reinterpret_cast<const ulonglong2*>(sh_w + jj * SH_W);
    const ulonglong2* wz4 = reinterpret_cast<const ulonglong2*>(sh_w + (8 + jj) * SH_W);
    const ulonglong2* wn4 = reinterpret_cast<const ulonglong2*>(sh_w + (16 + jj) * SH_W);
    const ulonglong2* h4a = reinterpret_cast<const ulonglong2*>(sh_h + b0 * SH_H);
    const ulonglong2* h4b = reinterpret_cast<const ulonglong2*>(sh_h + b1 * SH_H);

    for (int s = 0; s < 1024; ++s) {
        const int t = dir ? (1023 - s) : s;

        // Prefetch gi (independent of h) before the barrier spin.
        const float* gp0 = gi + ((size_t)t * BATCH + b0) * G3;
        const float* gp1 = gi + ((size_t)t * BATCH + b1) * G3;
        const float xr0 = __ldcs(gp0 + j);
        const float xz0 = __ldcs(gp0 + 512 + j);
        const float xn0 = __ldcs(gp0 + 1024 + j);
        const float xr1 = __ldcs(gp1 + j);
        const float xz1 = __ldcs(gp1 + 512 + j);
        const float xn1 = __ldcs(gp1 + 1024 + j);

        // Wait for h_{s-1}: every producer CTA of this direction posted flag >= s.
        if (s > 0 && tid < 64) {
            while (flags[tid * 32] < s) { }
        }
        __syncthreads();

        // Cooperative gather of full h (32x512) into SMEM.
        const float4* src4 = (s == 0)
            ? reinterpret_cast<const float4*>(h0)
            : reinterpret_cast<const float4*>(&g_hbuf[dir][s & 1][0]);
#pragma unroll
        for (int i = 0; i < 32; ++i) {
            int flat = tid + i * 128;            // 0..4095 float4s
            reinterpret_cast<float4*>(sh_h)[(flat >> 7) * (SH_H / 4) + (flat & 127)] =
                __ldcg(src4 + flat);
        }
        __syncthreads();

        // Packed f32x2 inner products: 3 gates x 2 batch rows.
        unsigned long long arx0 = 0, ary0 = 0, azx0 = 0, azy0 = 0, anx0 = 0, any0 = 0;
        unsigned long long arx1 = 0, ary1 = 0, azx1 = 0, azy1 = 0, anx1 = 0, any1 = 0;
#pragma unroll 4
        for (int kq = 0; kq < 128; ++kq) {
            ulonglong2 ha = h4a[kq];
            ulonglong2 hb = h4b[kq];
            ulonglong2 wr = wr4[kq];
            ulonglong2 wz = wz4[kq];
            ulonglong2 wn = wn4[kq];
            FMA2(arx0, ha.x, wr.x); FMA2(ary0, ha.y, wr.y);
            FMA2(azx0, ha.x, wz.x); FMA2(azy0, ha.y, wz.y);
            FMA2(anx0, ha.x, wn.x); FMA2(any0, ha.y, wn.y);
            FMA2(arx1, hb.x, wr.x); FMA2(ary1, hb.y, wr.y);
            FMA2(azx1, hb.x, wz.x); FMA2(azy1, hb.y, wz.y);
            FMA2(anx1, hb.x, wn.x); FMA2(any1, hb.y, wn.y);
        }
        const float ar0 = rsum2(arx0, ary0), az0 = rsum2(azx0, azy0), an0 = rsum2(anx0, any0);
        const float ar1 = rsum2(arx1, ary1), az1 = rsum2(azx1, azy1), an1 = rsum2(anx1, any1);

        float* hdst = &g_hbuf[dir][(s + 1) & 1][0];
        {
            const float r = 1.f / (1.f + __expf(-(xr0 + bir + ar0 + bhr)));
            const float z = 1.f / (1.f + __expf(-(xz0 + biz + az0 + bhz)));
            const float n = tanhf(xn0 + bin_ + r * (an0 + bhn));
            const float hold = sh_h[b0 * SH_H + j];
            const float hn = (1.f - z) * n + z * hold;
            hdst[b0 * HID + j] = hn;
            out[((size_t)t * BATCH + b0) * 1024 + dir * 512 + j] = hn;
            if (s == 1023) fin[b0 * HID + j] = hn;
        }
        {
            const float r = 1.f / (1.f + __expf(-(xr1 + bir + ar1 + bhr)));
            const float z = 1.f / (1.f + __expf(-(xz1 + biz + az1 + bhz)));
            const float n = tanhf(xn1 + bin_ + r * (an1 + bhn));
            const float hold = sh_h[b1 * SH_H + j];
            const float hn = (1.f - z) * n + z * hold;
            hdst[b1 * HID + j] = hn;
            out[((size_t)t * BATCH + b1) * 1024 + dir * 512 + j] = hn;
            if (s == 1023) fin[b1 * HID + j] = hn;
        }

        // Publish: fence all threads' h stores, then post this CTA's flag.
        __threadfence();
        __syncthreads();
        if (tid == 0) flags[cta * 32] = s + 1;
    }
}

// ---------------------------------------------------------------------------
extern "C" void kernel_launch(void* const* d_in, const int* in_sizes, int n_in,
                              void* d_out, int out_size)
{
    const float* x  = (const float*)d_in[0];
    const float* h0 = (const float*)d_in[1];
    float* out    = (float*)d_out;
    float* finals = out + (size_t)TBm * 1024;

    float* gi_base; float* buf_base; void* flagp;
    cudaGetSymbolAddress((void**)&gi_base, g_gi);
    cudaGetSymbolAddress((void**)&buf_base, g_buf);
    cudaGetSymbolAddress(&flagp, g_flags);
    float* gi_f = gi_base;
    float* gi_b = gi_base + (size_t)TBm * G3;
    float* bufA = buf_base;
    float* bufB = buf_base + (size_t)TBm * 1024;

    cudaFuncSetAttribute(gru_scan, cudaFuncAttributeMaxDynamicSharedMemorySize,
                         SMEM_BYTES);

    const float* lin = x;
    int K = 256;
    for (int layer = 0; layer < 3; ++layer) {
        const float* wih_f = (const float*)d_in[2 + 8 * layer + 0];
        const float* whh_f = (const float*)d_in[2 + 8 * layer + 1];
        const float* bih_f = (const float*)d_in[2 + 8 * layer + 2];
        const float* bhh_f = (const float*)d_in[2 + 8 * layer + 3];
        const float* wih_b = (const float*)d_in[2 + 8 * layer + 4];
        const float* whh_b = (const float*)d_in[2 + 8 * layer + 5];
        const float* bih_b = (const float*)d_in[2 + 8 * layer + 6];
        const float* bhh_b = (const float*)d_in[2 + 8 * layer + 7];

        dim3 grid(G3 / 64, TBm / 64);
        gi_gemm<<<grid, 128>>>(lin, wih_f, gi_f, K);
        gi_gemm<<<grid, 128>>>(lin, wih_b, gi_b, K);

        cudaMemsetAsync(flagp, 0, sizeof(int) * 2 * 64 * 32);

        float* lout = (layer == 0) ? bufA : (layer == 1) ? bufB : out;
        gru_scan<<<128, 128, SMEM_BYTES>>>(
            gi_f, gi_b, whh_f, whh_b,
            bih_f, bhh_f, bih_b, bhh_b,
            h0 + (size_t)(2 * layer) * BATCH * HID,
            h0 + (size_t)(2 * layer + 1) * BATCH * HID,
            lout,
            finals + (size_t)(2 * layer) * BATCH * HID,
            finals + (size_t)(2 * layer + 1) * BATCH * HID);

        lin = lout;
        K = 1024;
    }
}